// round 4
// baseline (speedup 1.0000x reference)
#include <cuda_runtime.h>
#include <cstdint>

#define NSEQ 1024
#define NRES 768
#define CM   64
#define XS   68     // K1 staging row stride (floats)

// per-column weighted_avg scratch: wa[r][64]
__device__ float g_wa[NRES * CM];

__device__ __forceinline__ void fma4(float4& a, float s, const float4 w) {
    a.x += s * w.x; a.y += s * w.y; a.z += s * w.z; a.w += s * w.w;
}
__device__ __forceinline__ void xadd4(float4& a, int m) {
    a.x += __shfl_xor_sync(0xffffffffu, a.x, m);
    a.y += __shfl_xor_sync(0xffffffffu, a.y, m);
    a.z += __shfl_xor_sync(0xffffffffu, a.z, m);
    a.w += __shfl_xor_sync(0xffffffffu, a.w, m);
}
__device__ __forceinline__ uint32_t f2tf32(float f) {
    uint32_t r;
    asm("cvt.rna.tf32.f32 %0, %1;" : "=r"(r) : "f"(f));
    return r;
}
__device__ __forceinline__ void mma_tf32(float4& d,
    uint32_t a0, uint32_t a1, uint32_t a2, uint32_t a3,
    uint32_t b0, uint32_t b1) {
    asm volatile("mma.sync.aligned.m16n8k8.row.col.f32.tf32.tf32.f32 "
        "{%0,%1,%2,%3}, {%4,%5,%6,%7}, {%8,%9}, {%0,%1,%2,%3};"
        : "+f"(d.x), "+f"(d.y), "+f"(d.z), "+f"(d.w)
        : "r"(a0), "r"(a1), "r"(a2), "r"(a3), "r"(b0), "r"(b1));
}
__device__ __forceinline__ float sigf(float x) {
    return __fdividef(1.f, 1.f + __expf(-x));
}
__device__ __forceinline__ uint32_t su32(const void* p) {
    return (uint32_t)__cvta_generic_to_shared(p);
}
__device__ __forceinline__ void cpasync16(uint32_t dst, const void* src) {
    asm volatile("cp.async.cg.shared.global [%0], [%1], 16;" :: "r"(dst), "l"(src));
}
#define CP_COMMIT() asm volatile("cp.async.commit_group;")
#define CP_WAIT(n)  asm volatile("cp.async.wait_group %0;" :: "n"(n))

// ---------------------------------------------------------------------------
// Kernel 1: per-column attention, cp.async double-buffered staging.
// grid = 768 (one per column r), 512 threads.
// ---------------------------------------------------------------------------
__global__ void __launch_bounds__(512, 1) msa_k1(
    const float* __restrict__ act,      // [S, R, C]
    const float* __restrict__ mask,     // [S, R]
    const float* __restrict__ ln_scale, const float* __restrict__ ln_bias,
    const float* __restrict__ query_w,  // [64, 64]
    const float* __restrict__ key_w,    // [64, 8]
    const float* __restrict__ value_w)  // [64, 8]
{
    extern __shared__ float sm[];
    float* xb0  = sm;               // 8704  : 128 rows x 68
    float* xb1  = xb0 + 8704;       // 8704
    float* ks   = xb1 + 8704;       // 8192
    float* vs   = ks + 8192;        // 8192
    float* lsm  = vs + 8192;        // 8192
    float* msk  = lsm + 8192;       // 1024
    float* kws  = msk + 1024;       // 512
    float* vws  = kws + 512;        // 512
    float* scl  = vws + 512;        // 64
    float* bia  = scl + 64;         // 64
    float* qsum = bia + 64;         // 64
    float* qf   = qsum + 64;        // 64
    float* red  = qf + 64;          // 128
    float* gmax = red + 128;        // 8
    float* invZ = gmax + 8;         // 8
    float* part = invZ + 8;         // 512
    float* Msum = part + 512;       // 1

    const int tid  = threadIdx.x;
    const int r    = blockIdx.x;
    const int lane = tid & 31;
    const int w    = tid >> 5;
    const int q    = tid >> 2;      // row within 128-row tile
    const int Q    = tid & 3;       // channel quarter (16 ch)

    if (tid < 512) { kws[tid] = key_w[tid]; vws[tid] = value_w[tid]; }
    if (tid < 64) { scl[tid] = ln_scale[tid]; bia[tid] = ln_bias[tid]; qsum[tid] = 0.f; }
    if (tid == 64) *Msum = 0.f;

    const uint32_t b0a = su32(xb0), b1a = su32(xb1);
    const int srow = tid >> 4, c16 = tid & 15;

    // prologue: stage tiles 0 and 1
#pragma unroll
    for (int rnd = 0; rnd < 4; rnd++) {
        const int row = rnd * 32 + srow;
        cpasync16(b0a + row * (XS*4) + c16 * 16,
                  act + ((size_t)row * NRES + r) * CM + c16 * 4);
    }
    CP_COMMIT();
#pragma unroll
    for (int rnd = 0; rnd < 4; rnd++) {
        const int row = rnd * 32 + srow;
        cpasync16(b1a + row * (XS*4) + c16 * 16,
                  act + ((size_t)(128 + row) * NRES + r) * CM + c16 * 4);
    }
    CP_COMMIT();
    __syncthreads();   // covers kws/scl init too

    const float4* kw4 = (const float4*)kws;
    const float4* vw4 = (const float4*)vws;

    float lqs[16];
#pragma unroll
    for (int i = 0; i < 16; i++) lqs[i] = 0.f;
    float lms = 0.f;

    for (int t = 0; t < 8; ++t) {
        if (t < 7) { CP_WAIT(1); } else { CP_WAIT(0); }
        __syncthreads();
        const float* buf = (t & 1) ? xb1 : xb0;

        const int s = t * 128 + q;
        // load 16 channels (swizzled float4 reads)
        float x[16];
#pragma unroll
        for (int i = 0; i < 4; i++) {
            const int ci = (i + q + Q) & 3;
            const float4 tt = *(const float4*)(buf + q * XS + Q * 16 + ci * 4);
            x[ci*4+0] = tt.x; x[ci*4+1] = tt.y; x[ci*4+2] = tt.z; x[ci*4+3] = tt.w;
        }
        float m = 0.f;
        if (Q == 0) { m = mask[(size_t)s * NRES + r]; msk[s] = m; lms += m; }
        m = __shfl_sync(0xffffffffu, m, lane & ~3);

        float sum = 0.f;
#pragma unroll
        for (int i = 0; i < 16; i++) sum += x[i];
        sum += __shfl_xor_sync(0xffffffffu, sum, 1);
        sum += __shfl_xor_sync(0xffffffffu, sum, 2);
        const float mu = sum * (1.f / 64.f);
        float vv = 0.f;
#pragma unroll
        for (int i = 0; i < 16; i++) { float d = x[i] - mu; vv += d * d; }
        vv += __shfl_xor_sync(0xffffffffu, vv, 1);
        vv += __shfl_xor_sync(0xffffffffu, vv, 2);
        const float rstd = rsqrtf(vv * (1.f / 64.f) + 1e-5f);

        float4 pk0 = {0,0,0,0}, pk1 = {0,0,0,0}, pv0 = {0,0,0,0}, pv1 = {0,0,0,0};
#pragma unroll
        for (int c = 0; c < 16; c++) {
            const int cg = Q * 16 + c;
            const float xn = (x[c] - mu) * rstd * scl[cg] + bia[cg];
            lqs[c] += m * xn;
            fma4(pk0, xn, kw4[cg*2]);   fma4(pk1, xn, kw4[cg*2+1]);
            fma4(pv0, xn, vw4[cg*2]);   fma4(pv1, xn, vw4[cg*2+1]);
        }
        xadd4(pk0, 1); xadd4(pk1, 1); xadd4(pv0, 1); xadd4(pv1, 1);
        xadd4(pk0, 2); xadd4(pk1, 2); xadd4(pv0, 2); xadd4(pv1, 2);
        if (Q == 0) {
            float4* kp = (float4*)(ks + s * 8);
            kp[0] = pk0; kp[1] = pk1;
        } else if (Q == 1) {
            float4* vp = (float4*)(vs + s * 8);
            vp[0] = pv0; vp[1] = pv1;
        }
        __syncthreads();
        if (t + 2 < 8) {
            const uint32_t ba = (t & 1) ? b1a : b0a;
#pragma unroll
            for (int rnd = 0; rnd < 4; rnd++) {
                const int row = rnd * 32 + srow;
                cpasync16(ba + row * (XS*4) + c16 * 16,
                          act + ((size_t)((t + 2) * 128 + row) * NRES + r) * CM + c16 * 4);
            }
            CP_COMMIT();
        }
    }

    // ---- qsum / Msum reductions ----
#pragma unroll
    for (int i = 0; i < 16; i++) {
        float v = lqs[i];
        v += __shfl_xor_sync(0xffffffffu, v, 4);
        v += __shfl_xor_sync(0xffffffffu, v, 8);
        v += __shfl_xor_sync(0xffffffffu, v, 16);
        lqs[i] = v;
    }
    if (lane < 4) {
#pragma unroll
        for (int i = 0; i < 16; i++) atomicAdd(&qsum[lane * 16 + i], lqs[i]);
    }
    lms += __shfl_xor_sync(0xffffffffu, lms, 4);
    lms += __shfl_xor_sync(0xffffffffu, lms, 8);
    lms += __shfl_xor_sync(0xffffffffu, lms, 16);
    if (lane == 0) atomicAdd(Msum, lms);
    __syncthreads();

    // ---- q projection ----
    if (tid < 64) {
        const float invM = 1.f / (*Msum + 1e-10f);
        float acc = 0.f;
        for (int c = 0; c < 64; c++) acc += qsum[c] * query_w[c * 64 + tid];
        qf[tid] = acc * invM * 0.35355339059327373f;
    }
    __syncthreads();

    // ---- logits + max ----
    float lmax[8];
#pragma unroll
    for (int h = 0; h < 8; h++) lmax[h] = -3.4e38f;
#pragma unroll
    for (int it = 0; it < 2; it++) {
        const int s = tid + it * 512;
        const float4* kp = (const float4*)(ks + s * 8);
        const float4 k0 = kp[0], k1 = kp[1];
        const float b = 1e9f * (msk[s] - 1.f);
#pragma unroll
        for (int h = 0; h < 8; h++) {
            const float* qv = qf + h * 8;
            float l = b + qv[0]*k0.x + qv[1]*k0.y + qv[2]*k0.z + qv[3]*k0.w
                        + qv[4]*k1.x + qv[5]*k1.y + qv[6]*k1.z + qv[7]*k1.w;
            lsm[s * 8 + h] = l;
            lmax[h] = fmaxf(lmax[h], l);
        }
    }
#pragma unroll
    for (int h = 0; h < 8; h++) {
#pragma unroll
        for (int off = 16; off; off >>= 1)
            lmax[h] = fmaxf(lmax[h], __shfl_xor_sync(0xffffffffu, lmax[h], off));
    }
    if (lane == 0) {
#pragma unroll
        for (int h = 0; h < 8; h++) red[w * 8 + h] = lmax[h];
    }
    __syncthreads();
    if (tid < 8) {
        float mm = red[tid];
#pragma unroll
        for (int ww = 1; ww < 16; ww++) mm = fmaxf(mm, red[ww * 8 + tid]);
        gmax[tid] = mm;
    }
    __syncthreads();

    // ---- exp + Z ----
    float zl[8];
#pragma unroll
    for (int h = 0; h < 8; h++) zl[h] = 0.f;
#pragma unroll
    for (int it = 0; it < 2; it++) {
        const int s = tid + it * 512;
#pragma unroll
        for (int h = 0; h < 8; h++) {
            const float e = __expf(lsm[s * 8 + h] - gmax[h]);
            lsm[s * 8 + h] = e;
            zl[h] += e;
        }
    }
#pragma unroll
    for (int h = 0; h < 8; h++) {
#pragma unroll
        for (int off = 16; off; off >>= 1)
            zl[h] += __shfl_xor_sync(0xffffffffu, zl[h], off);
    }
    if (lane == 0) {
#pragma unroll
        for (int h = 0; h < 8; h++) red[w * 8 + h] = zl[h];
    }
    __syncthreads();
    if (tid < 8) {
        float z = 0.f;
#pragma unroll
        for (int ww = 0; ww < 16; ww++) z += red[ww * 8 + tid];
        invZ[tid] = 1.f / z;
    }
    __syncthreads();

    // ---- weighted_avg ----
    {
        const int hd = tid & 63, q8 = tid >> 6;
        const int h = hd >> 3, d = hd & 7;
        float pa = 0.f;
        const int sb = q8 * 128;
        for (int s = sb; s < sb + 128; ++s)
            pa += lsm[s * 8 + h] * vs[s * 8 + d];
        part[tid] = pa;
    }
    __syncthreads();
    if (tid < 64) {
        const int h = tid >> 3;
        float acc = 0.f;
#pragma unroll
        for (int k = 0; k < 8; k++) acc += part[tid + 64 * k];
        g_wa[r * 64 + tid] = acc * invZ[h];
    }
}

// ---------------------------------------------------------------------------
// Kernel 2: gate + output via tf32 MMA, fragment-packed smem, M=32 per warp.
// grid = (768, 4 tiles of 256 rows), 256 threads (8 warps x 32 rows).
// Fragment layout per 16-row strip: frag[k][lane][4] (a0,a1,a2,a3), k-stride
// 136 floats; strip region (1088 floats) doubles as 16x68 row-major for STG.
// ---------------------------------------------------------------------------
#define KST 136
#define SST 1088

__global__ void __launch_bounds__(256, 2) msa_k2(
    const float* __restrict__ act,
    const float* __restrict__ ln_scale, const float* __restrict__ ln_bias,
    const float* __restrict__ gating_w,  // [64, 64]  (c, j)
    const float* __restrict__ gating_b,  // [64]
    const float* __restrict__ output_w,  // [64, 64]  (j, o)
    const float* __restrict__ output_b,  // [64]
    float* __restrict__ out)             // [S, R, C]
{
    extern __shared__ float sm2[];
    float* xnf = sm2;              // 16 strips * 1088 = 17408
    float* gwf = xnf + 17408;      // 4096 : B-frag [n][k][lane] float2
    float* owf = gwf + 4096;       // 4096
    float* was = owf + 4096;       // 64
    float* gbs = was + 64;         // 64
    float* obs = gbs + 64;         // 64
    float* scl = obs + 64;         // 64
    float* bia = scl + 64;         // 64

    const int tid  = threadIdx.x;
    const int r    = blockIdx.x;
    const int s0   = blockIdx.y * 256;
    const int w    = tid >> 5, lane = tid & 31;
    const int c4   = lane & 15, rsel = lane >> 4;
    const int g    = lane >> 2, t = lane & 3;

    // ---- stage weights into B-fragment layout ----
    for (int i = tid; i < 4096; i += 256) {
        const int c = i >> 6, j = i & 63;          // first, second index
        const int kk = c >> 3, tt = c & 7;
        const int nn = j >> 3, gg = j & 7;
        const int off = ((nn * 8 + kk) * 32 + gg * 4 + (tt & 3)) * 2 + (tt >> 2);
        gwf[off] = __uint_as_float(f2tf32(gating_w[i]));   // b = GW[c][j]
        owf[off] = __uint_as_float(f2tf32(output_w[i]));   // b = OW[j][o]: c=j, j=o
    }
    if (tid < 64) {
        was[tid] = g_wa[r * 64 + tid];
        gbs[tid] = gating_b[tid];  obs[tid] = output_b[tid];
        scl[tid] = ln_scale[tid];  bia[tid] = ln_bias[tid];
    }
    __syncthreads();

    // ---- LN: warp owns rows w*32..w*32+31 (strips 2w, 2w+1), fragment scatter ----
    {
        const float4 sc = ((const float4*)scl)[c4];
        const float4 bi = ((const float4*)bia)[c4];
        const int kf = c4 >> 1, slot = (c4 & 1) * 2;
#pragma unroll
        for (int rnd = 0; rnd < 16; rnd++) {
            const int row = w * 32 + rnd * 2 + rsel;
            const float4 tt = *(const float4*)(act + ((size_t)(s0 + row) * NRES + r) * CM + c4 * 4);
            float sum = tt.x + tt.y + tt.z + tt.w;
            sum += __shfl_xor_sync(0xffffffffu, sum, 1);
            sum += __shfl_xor_sync(0xffffffffu, sum, 2);
            sum += __shfl_xor_sync(0xffffffffu, sum, 4);
            sum += __shfl_xor_sync(0xffffffffu, sum, 8);
            const float mu = sum * (1.f / 64.f);
            float vv = (tt.x-mu)*(tt.x-mu) + (tt.y-mu)*(tt.y-mu)
                     + (tt.z-mu)*(tt.z-mu) + (tt.w-mu)*(tt.w-mu);
            vv += __shfl_xor_sync(0xffffffffu, vv, 1);
            vv += __shfl_xor_sync(0xffffffffu, vv, 2);
            vv += __shfl_xor_sync(0xffffffffu, vv, 4);
            vv += __shfl_xor_sync(0xffffffffu, vv, 8);
            const float rstd = rsqrtf(vv * (1.f / 64.f) + 1e-5f);
            const int rowin = row & 15, st = row >> 4;
            float* base = xnf + st * SST + kf * KST + (slot + (rowin >> 3));
            const int g2 = rowin & 7;
            base[(g2*4+0)*4] = __uint_as_float(f2tf32((tt.x - mu) * rstd * sc.x + bi.x));
            base[(g2*4+1)*4] = __uint_as_float(f2tf32((tt.y - mu) * rstd * sc.y + bi.y));
            base[(g2*4+2)*4] = __uint_as_float(f2tf32((tt.z - mu) * rstd * sc.z + bi.z));
            base[(g2*4+3)*4] = __uint_as_float(f2tf32((tt.w - mu) * rstd * sc.w + bi.w));
        }
    }
    __syncwarp();   // strips are warp-private

    float* st0 = xnf + (2 * w) * SST;
    float* st1 = st0 + SST;

    // ---- GEMM1: logits = XN @ GW (2 strips x 8 n-tiles) ----
    float4 acc0[8], acc1[8];
#pragma unroll
    for (int n = 0; n < 8; n++) { acc0[n] = make_float4(0,0,0,0); acc1[n] = make_float4(0,0,0,0); }
#pragma unroll
    for (int k = 0; k < 8; k++) {
        const float4 A0 = *(const float4*)(st0 + k * KST + lane * 4);
        const float4 A1 = *(const float4*)(st1 + k * KST + lane * 4);
#pragma unroll
        for (int n = 0; n < 8; n++) {
            const float2 b = *(const float2*)(gwf + ((n * 8 + k) * 32 + lane) * 2);
            mma_tf32(acc0[n], __float_as_uint(A0.x), __float_as_uint(A0.y),
                     __float_as_uint(A0.z), __float_as_uint(A0.w),
                     __float_as_uint(b.x), __float_as_uint(b.y));
            mma_tf32(acc1[n], __float_as_uint(A1.x), __float_as_uint(A1.y),
                     __float_as_uint(A1.z), __float_as_uint(A1.w),
                     __float_as_uint(b.x), __float_as_uint(b.y));
        }
    }
    __syncwarp();

    // ---- gate: G = wa*sigmoid(logit+gb), scatter into fragment layout ----
    {
        const int l0 = 4 * g + ((2 * t) & 3),     s0b = (2 * t) & 4 ? 2 : 0;
        const int l1 = 4 * g + ((2 * t + 1) & 3), s1b = (2 * t + 1) & 4 ? 2 : 0;
#pragma unroll
        for (int n = 0; n < 8; n++) {
            const int c0 = n * 8 + 2 * t, c1 = c0 + 1;
            const float w0 = was[c0], w1 = was[c1];
            const float b0 = gbs[c0], b1 = gbs[c1];
            float2 p0, p1, q0, q1;
            p0.x = __uint_as_float(f2tf32(w0 * sigf(acc0[n].x + b0)));   // row g,   c0
            p0.y = __uint_as_float(f2tf32(w0 * sigf(acc0[n].z + b0)));   // row g+8, c0
            p1.x = __uint_as_float(f2tf32(w1 * sigf(acc0[n].y + b1)));   // row g,   c1
            p1.y = __uint_as_float(f2tf32(w1 * sigf(acc0[n].w + b1)));
            q0.x = __uint_as_float(f2tf32(w0 * sigf(acc1[n].x + b0)));
            q0.y = __uint_as_float(f2tf32(w0 * sigf(acc1[n].z + b0)));
            q1.x = __uint_as_float(f2tf32(w1 * sigf(acc1[n].y + b1)));
            q1.y = __uint_as_float(f2tf32(w1 * sigf(acc1[n].w + b1)));
            *(float2*)(st0 + n * KST + l0 * 4 + s0b) = p0;
            *(float2*)(st0 + n * KST + l1 * 4 + s1b) = p1;
            *(float2*)(st1 + n * KST + l0 * 4 + s0b) = q0;
            *(float2*)(st1 + n * KST + l1 * 4 + s1b) = q1;
        }
    }
    __syncwarp();

    // ---- GEMM2: OUT = G @ OW + ob ----
    float4 o0[8], o1[8];
#pragma unroll
    for (int n = 0; n < 8; n++) {
        const int c0 = n * 8 + 2 * t;
        o0[n] = make_float4(obs[c0], obs[c0+1], obs[c0], obs[c0+1]);
        o1[n] = o0[n];
    }
#pragma unroll
    for (int k = 0; k < 8; k++) {
        const float4 A0 = *(const float4*)(st0 + k * KST + lane * 4);
        const float4 A1 = *(const float4*)(st1 + k * KST + lane * 4);
#pragma unroll
        for (int n = 0; n < 8; n++) {
            const float2 b = *(const float2*)(owf + ((n * 8 + k) * 32 + lane) * 2);
            mma_tf32(o0[n], __float_as_uint(A0.x), __float_as_uint(A0.y),
                     __float_as_uint(A0.z), __float_as_uint(A0.w),
                     __float_as_uint(b.x), __float_as_uint(b.y));
            mma_tf32(o1[n], __float_as_uint(A1.x), __float_as_uint(A1.y),
                     __float_as_uint(A1.z), __float_as_uint(A1.w),
                     __float_as_uint(b.x), __float_as_uint(b.y));
        }
    }
    __syncwarp();

    // ---- stage outputs row-major into the same strip region ----
#pragma unroll
    for (int n = 0; n < 8; n++) {
        const int c0 = n * 8 + 2 * t;
        *(float2*)(st0 + g * 68 + c0)       = make_float2(o0[n].x, o0[n].y);
        *(float2*)(st0 + (g + 8) * 68 + c0) = make_float2(o0[n].z, o0[n].w);
        *(float2*)(st1 + g * 68 + c0)       = make_float2(o1[n].x, o1[n].y);
        *(float2*)(st1 + (g + 8) * 68 + c0) = make_float2(o1[n].z, o1[n].w);
    }
    __syncwarp();

    // ---- coalesced STG ----
#pragma unroll
    for (int rnd = 0; rnd < 16; rnd++) {
        const int row = w * 32 + rnd * 2 + rsel;
        const int st = row >> 4, rowin = row & 15;
        const float4 v = *(const float4*)(xnf + st * SST + rowin * 68 + c4 * 4);
        *(float4*)(out + ((size_t)(s0 + row) * NRES + r) * CM + c4 * 4) = v;
    }
}

// ---------------------------------------------------------------------------
#define K1_SMEM (44945 * 4)
#define K2_SMEM (25920 * 4)

extern "C" void kernel_launch(void* const* d_in, const int* in_sizes, int n_in,
                              void* d_out, int out_size) {
    (void)in_sizes; (void)n_in; (void)out_size;
    const float* act      = (const float*)d_in[0];
    const float* mask     = (const float*)d_in[1];
    const float* ln_scale = (const float*)d_in[2];
    const float* ln_bias  = (const float*)d_in[3];
    const float* query_w  = (const float*)d_in[4];
    const float* key_w    = (const float*)d_in[5];
    const float* value_w  = (const float*)d_in[6];
    const float* gating_w = (const float*)d_in[7];
    const float* gating_b = (const float*)d_in[8];
    const float* output_w = (const float*)d_in[9];
    const float* output_b = (const float*)d_in[10];
    float* out = (float*)d_out;

    cudaFuncSetAttribute(msa_k1, cudaFuncAttributeMaxDynamicSharedMemorySize, K1_SMEM);
    cudaFuncSetAttribute(msa_k2, cudaFuncAttributeMaxDynamicSharedMemorySize, K2_SMEM);

    msa_k1<<<NRES, 512, K1_SMEM>>>(act, mask, ln_scale, ln_bias, query_w, key_w, value_w);
    msa_k2<<<dim3(NRES, 4), 256, K2_SMEM>>>(act, ln_scale, ln_bias,
                                            gating_w, gating_b, output_w, output_b, out);
}

// round 5
// speedup vs baseline: 1.9831x; 1.9831x over previous
#include <cuda_runtime.h>
#include <cstdint>

#define NSEQ 1024
#define NRES 768
#define CM   64

// per-column weighted_avg scratch: wa[r][64]
__device__ float g_wa[NRES * CM];

__device__ __forceinline__ void fma4(float4& a, float s, const float4 w) {
    a.x += s * w.x; a.y += s * w.y; a.z += s * w.z; a.w += s * w.w;
}
__device__ __forceinline__ void xadd4(float4& a, int m) {
    a.x += __shfl_xor_sync(0xffffffffu, a.x, m);
    a.y += __shfl_xor_sync(0xffffffffu, a.y, m);
    a.z += __shfl_xor_sync(0xffffffffu, a.z, m);
    a.w += __shfl_xor_sync(0xffffffffu, a.w, m);
}
__device__ __forceinline__ uint32_t f2tf32(float f) {
    uint32_t r;
    asm("cvt.rna.tf32.f32 %0, %1;" : "=r"(r) : "f"(f));
    return r;
}
__device__ __forceinline__ void mma_tf32(float4& d,
    uint32_t a0, uint32_t a1, uint32_t a2, uint32_t a3,
    uint32_t b0, uint32_t b1) {
    asm volatile("mma.sync.aligned.m16n8k8.row.col.f32.tf32.tf32.f32 "
        "{%0,%1,%2,%3}, {%4,%5,%6,%7}, {%8,%9}, {%0,%1,%2,%3};"
        : "+f"(d.x), "+f"(d.y), "+f"(d.z), "+f"(d.w)
        : "r"(a0), "r"(a1), "r"(a2), "r"(a3), "r"(b0), "r"(b1));
}
__device__ __forceinline__ float sigf(float x) {
    return __fdividef(1.f, 1.f + __expf(-x));
}

// ---------------------------------------------------------------------------
// Kernel 1: per-column attention (Round-1 structure, occupancy 2).
// grid = 768 blocks (one per column r), 256 threads.
// ---------------------------------------------------------------------------
__global__ void __launch_bounds__(256, 2) msa_k1(
    const float* __restrict__ act,      // [S, R, C]
    const float* __restrict__ mask,     // [S, R]
    const float* __restrict__ ln_scale, // [64]
    const float* __restrict__ ln_bias,  // [64]
    const float* __restrict__ query_w,  // [64, 64]
    const float* __restrict__ key_w,    // [64, 8]
    const float* __restrict__ value_w)  // [64, 8]
{
    extern __shared__ float sm[];
    float* ks   = sm;              // 8192  : k[s][8]
    float* vs   = ks + 8192;       // 8192  : v[s][8]
    float* lsm  = vs + 8192;       // 8192  : logits / exp [s][8]
    float* msk  = lsm + 8192;      // 1024
    float* kws  = msk + 1024;      // 512
    float* vws  = kws + 512;       // 512
    float* scl  = vws + 512;       // 64
    float* bia  = scl + 64;        // 64
    float* qsum = bia + 64;        // 64
    float* qf   = qsum + 64;       // 64
    float* red  = qf + 64;         // 64   (8 warps x 8 heads)
    float* gmax = red + 64;        // 8
    float* invZ = gmax + 8;        // 8
    float* part = invZ + 8;        // 256
    float* Msum = part + 256;      // 1

    const int tid  = threadIdx.x;
    const int r    = blockIdx.x;
    const int lane = tid & 31;
    const int half = tid & 1;      // which 32-channel half this thread owns
    const int pair = tid >> 1;     // row-pair index 0..127

    for (int i = tid; i < 512; i += 256) { kws[i] = key_w[i]; vws[i] = value_w[i]; }
    if (tid < 64) { scl[tid] = ln_scale[tid]; bia[tid] = ln_bias[tid]; qsum[tid] = 0.f; }
    if (tid == 64) *Msum = 0.f;
    __syncthreads();

    const float4* kw4 = (const float4*)kws;
    const float4* vw4 = (const float4*)vws;

    float lqs[32];
#pragma unroll
    for (int i = 0; i < 32; i++) lqs[i] = 0.f;
    float lms = 0.f;

    for (int it = 0; it < 8; ++it) {
        const int s = pair + it * 128;
        const float4* xp = (const float4*)(act + ((size_t)s * NRES + r) * CM) + half * 8;
        float x[32];
#pragma unroll
        for (int i = 0; i < 8; i++) {
            float4 t = xp[i];
            x[i*4+0] = t.x; x[i*4+1] = t.y; x[i*4+2] = t.z; x[i*4+3] = t.w;
        }
        const float m = mask[(size_t)s * NRES + r];
        if (half == 0) { msk[s] = m; lms += m; }

        float sum = 0.f;
#pragma unroll
        for (int i = 0; i < 32; i++) sum += x[i];
        sum += __shfl_xor_sync(0xffffffffu, sum, 1);
        const float mu = sum * (1.f / 64.f);

        float vv = 0.f;
#pragma unroll
        for (int i = 0; i < 32; i++) { float d = x[i] - mu; vv += d * d; }
        vv += __shfl_xor_sync(0xffffffffu, vv, 1);
        const float rstd = rsqrtf(vv * (1.f / 64.f) + 1e-5f);

        float4 pk0 = {0,0,0,0}, pk1 = {0,0,0,0}, pv0 = {0,0,0,0}, pv1 = {0,0,0,0};
#pragma unroll
        for (int c = 0; c < 32; c++) {
            const int cg = half * 32 + c;
            const float xn = (x[c] - mu) * rstd * scl[cg] + bia[cg];
            lqs[c] += m * xn;
            fma4(pk0, xn, kw4[cg*2]);   fma4(pk1, xn, kw4[cg*2+1]);
            fma4(pv0, xn, vw4[cg*2]);   fma4(pv1, xn, vw4[cg*2+1]);
        }
        xadd4(pk0, 1); xadd4(pk1, 1); xadd4(pv0, 1); xadd4(pv1, 1);
        if (half == 0) {
            float4* kp = (float4*)(ks + s * 8);
            kp[0] = pk0; kp[1] = pk1;
        } else {
            float4* vp = (float4*)(vs + s * 8);
            vp[0] = pv0; vp[1] = pv1;
        }
    }

#pragma unroll
    for (int i = 0; i < 32; i++) {
        float v = lqs[i];
        v += __shfl_xor_sync(0xffffffffu, v, 2);
        v += __shfl_xor_sync(0xffffffffu, v, 4);
        v += __shfl_xor_sync(0xffffffffu, v, 8);
        v += __shfl_xor_sync(0xffffffffu, v, 16);
        lqs[i] = v;
    }
    if (lane < 2) {
#pragma unroll
        for (int i = 0; i < 32; i++) atomicAdd(&qsum[lane * 32 + i], lqs[i]);
    }
    lms += __shfl_xor_sync(0xffffffffu, lms, 1);
    lms += __shfl_xor_sync(0xffffffffu, lms, 2);
    lms += __shfl_xor_sync(0xffffffffu, lms, 4);
    lms += __shfl_xor_sync(0xffffffffu, lms, 8);
    lms += __shfl_xor_sync(0xffffffffu, lms, 16);
    if (lane == 0) atomicAdd(Msum, lms);
    __syncthreads();

    if (tid < 64) {
        const float invM = 1.f / (*Msum + 1e-10f);
        float acc = 0.f;
        for (int c = 0; c < 64; c++) acc += qsum[c] * query_w[c * 64 + tid];
        qf[tid] = acc * invM * 0.35355339059327373f;
    }
    __syncthreads();

    float lmax[8];
#pragma unroll
    for (int h = 0; h < 8; h++) lmax[h] = -3.4e38f;
#pragma unroll
    for (int it = 0; it < 4; it++) {
        const int s = tid + it * 256;
        const float4* kp = (const float4*)(ks + s * 8);
        const float4 k0 = kp[0], k1 = kp[1];
        const float b = 1e9f * (msk[s] - 1.f);
#pragma unroll
        for (int h = 0; h < 8; h++) {
            const float* q = qf + h * 8;
            float l = b + q[0]*k0.x + q[1]*k0.y + q[2]*k0.z + q[3]*k0.w
                        + q[4]*k1.x + q[5]*k1.y + q[6]*k1.z + q[7]*k1.w;
            lsm[s * 8 + h] = l;
            lmax[h] = fmaxf(lmax[h], l);
        }
    }
    const int w = tid >> 5;
#pragma unroll
    for (int h = 0; h < 8; h++) {
#pragma unroll
        for (int off = 16; off; off >>= 1)
            lmax[h] = fmaxf(lmax[h], __shfl_xor_sync(0xffffffffu, lmax[h], off));
    }
    if (lane == 0) {
#pragma unroll
        for (int h = 0; h < 8; h++) red[w * 8 + h] = lmax[h];
    }
    __syncthreads();
    if (tid < 8) {
        float mm = red[tid];
#pragma unroll
        for (int ww = 1; ww < 8; ww++) mm = fmaxf(mm, red[ww * 8 + tid]);
        gmax[tid] = mm;
    }
    __syncthreads();

    float zl[8];
#pragma unroll
    for (int h = 0; h < 8; h++) zl[h] = 0.f;
#pragma unroll
    for (int it = 0; it < 4; it++) {
        const int s = tid + it * 256;
#pragma unroll
        for (int h = 0; h < 8; h++) {
            const float e = __expf(lsm[s * 8 + h] - gmax[h]);
            lsm[s * 8 + h] = e;
            zl[h] += e;
        }
    }
#pragma unroll
    for (int h = 0; h < 8; h++) {
#pragma unroll
        for (int off = 16; off; off >>= 1)
            zl[h] += __shfl_xor_sync(0xffffffffu, zl[h], off);
    }
    if (lane == 0) {
#pragma unroll
        for (int h = 0; h < 8; h++) red[w * 8 + h] = zl[h];
    }
    __syncthreads();
    if (tid < 8) {
        float z = 0.f;
#pragma unroll
        for (int ww = 0; ww < 8; ww++) z += red[ww * 8 + tid];
        invZ[tid] = 1.f / z;
    }
    __syncthreads();

    {
        const int hd = tid & 63, q4 = tid >> 6;
        const int h = hd >> 3, d = hd & 7;
        float p = 0.f;
        const int s0 = q4 * 256;
        for (int s = s0; s < s0 + 256; ++s)
            p += lsm[s * 8 + h] * vs[s * 8 + d];
        part[tid] = p;
    }
    __syncthreads();
    if (tid < 64) {
        const int h = tid >> 3;
        g_wa[r * 64 + tid] =
            (part[tid] + part[tid + 64] + part[tid + 128] + part[tid + 192]) * invZ[h];
    }
}

// ---------------------------------------------------------------------------
// Kernel 2: gate + output via tf32 MMA, fragment-packed smem, M=32 per warp.
// (Round-4 version, measured 199 us)
// ---------------------------------------------------------------------------
#define KST 136
#define SST 1088

__global__ void __launch_bounds__(256, 2) msa_k2(
    const float* __restrict__ act,
    const float* __restrict__ ln_scale, const float* __restrict__ ln_bias,
    const float* __restrict__ gating_w,  // [64, 64]  (c, j)
    const float* __restrict__ gating_b,  // [64]
    const float* __restrict__ output_w,  // [64, 64]  (j, o)
    const float* __restrict__ output_b,  // [64]
    float* __restrict__ out)             // [S, R, C]
{
    extern __shared__ float sm2[];
    float* xnf = sm2;              // 16 strips * 1088 = 17408
    float* gwf = xnf + 17408;      // 4096 : B-frag [n][k][lane] float2
    float* owf = gwf + 4096;       // 4096
    float* was = owf + 4096;       // 64
    float* gbs = was + 64;         // 64
    float* obs = gbs + 64;         // 64
    float* scl = obs + 64;         // 64
    float* bia = scl + 64;         // 64

    const int tid  = threadIdx.x;
    const int r    = blockIdx.x;
    const int s0   = blockIdx.y * 256;
    const int w    = tid >> 5, lane = tid & 31;
    const int c4   = lane & 15, rsel = lane >> 4;
    const int g    = lane >> 2, t = lane & 3;

    // ---- stage weights into B-fragment layout ----
    for (int i = tid; i < 4096; i += 256) {
        const int c = i >> 6, j = i & 63;
        const int kk = c >> 3, tt = c & 7;
        const int nn = j >> 3, gg = j & 7;
        const int off = ((nn * 8 + kk) * 32 + gg * 4 + (tt & 3)) * 2 + (tt >> 2);
        gwf[off] = __uint_as_float(f2tf32(gating_w[i]));
        owf[off] = __uint_as_float(f2tf32(output_w[i]));
    }
    if (tid < 64) {
        was[tid] = g_wa[r * 64 + tid];
        gbs[tid] = gating_b[tid];  obs[tid] = output_b[tid];
        scl[tid] = ln_scale[tid];  bia[tid] = ln_bias[tid];
    }
    __syncthreads();

    // ---- LN: warp owns rows w*32..w*32+31 (strips 2w, 2w+1) ----
    {
        const float4 sc = ((const float4*)scl)[c4];
        const float4 bi = ((const float4*)bia)[c4];
        const int kf = c4 >> 1, slot = (c4 & 1) * 2;
#pragma unroll
        for (int rnd = 0; rnd < 16; rnd++) {
            const int row = w * 32 + rnd * 2 + rsel;
            const float4 tt = *(const float4*)(act + ((size_t)(s0 + row) * NRES + r) * CM + c4 * 4);
            float sum = tt.x + tt.y + tt.z + tt.w;
            sum += __shfl_xor_sync(0xffffffffu, sum, 1);
            sum += __shfl_xor_sync(0xffffffffu, sum, 2);
            sum += __shfl_xor_sync(0xffffffffu, sum, 4);
            sum += __shfl_xor_sync(0xffffffffu, sum, 8);
            const float mu = sum * (1.f / 64.f);
            float vv = (tt.x-mu)*(tt.x-mu) + (tt.y-mu)*(tt.y-mu)
                     + (tt.z-mu)*(tt.z-mu) + (tt.w-mu)*(tt.w-mu);
            vv += __shfl_xor_sync(0xffffffffu, vv, 1);
            vv += __shfl_xor_sync(0xffffffffu, vv, 2);
            vv += __shfl_xor_sync(0xffffffffu, vv, 4);
            vv += __shfl_xor_sync(0xffffffffu, vv, 8);
            const float rstd = rsqrtf(vv * (1.f / 64.f) + 1e-5f);
            const int rowin = row & 15, st = row >> 4;
            float* base = xnf + st * SST + kf * KST + (slot + (rowin >> 3));
            const int g2 = rowin & 7;
            base[(g2*4+0)*4] = __uint_as_float(f2tf32((tt.x - mu) * rstd * sc.x + bi.x));
            base[(g2*4+1)*4] = __uint_as_float(f2tf32((tt.y - mu) * rstd * sc.y + bi.y));
            base[(g2*4+2)*4] = __uint_as_float(f2tf32((tt.z - mu) * rstd * sc.z + bi.z));
            base[(g2*4+3)*4] = __uint_as_float(f2tf32((tt.w - mu) * rstd * sc.w + bi.w));
        }
    }
    __syncwarp();

    float* st0 = xnf + (2 * w) * SST;
    float* st1 = st0 + SST;

    // ---- GEMM1: logits = XN @ GW ----
    float4 acc0[8], acc1[8];
#pragma unroll
    for (int n = 0; n < 8; n++) { acc0[n] = make_float4(0,0,0,0); acc1[n] = make_float4(0,0,0,0); }
#pragma unroll
    for (int k = 0; k < 8; k++) {
        const float4 A0 = *(const float4*)(st0 + k * KST + lane * 4);
        const float4 A1 = *(const float4*)(st1 + k * KST + lane * 4);
#pragma unroll
        for (int n = 0; n < 8; n++) {
            const float2 b = *(const float2*)(gwf + ((n * 8 + k) * 32 + lane) * 2);
            mma_tf32(acc0[n], __float_as_uint(A0.x), __float_as_uint(A0.y),
                     __float_as_uint(A0.z), __float_as_uint(A0.w),
                     __float_as_uint(b.x), __float_as_uint(b.y));
            mma_tf32(acc1[n], __float_as_uint(A1.x), __float_as_uint(A1.y),
                     __float_as_uint(A1.z), __float_as_uint(A1.w),
                     __float_as_uint(b.x), __float_as_uint(b.y));
        }
    }
    __syncwarp();

    // ---- gate: G = wa*sigmoid(logit+gb), scatter into fragment layout ----
    {
        const int l0 = 4 * g + ((2 * t) & 3),     s0b = (2 * t) & 4 ? 2 : 0;
        const int l1 = 4 * g + ((2 * t + 1) & 3), s1b = (2 * t + 1) & 4 ? 2 : 0;
#pragma unroll
        for (int n = 0; n < 8; n++) {
            const int c0 = n * 8 + 2 * t, c1 = c0 + 1;
            const float w0 = was[c0], w1 = was[c1];
            const float b0 = gbs[c0], b1 = gbs[c1];
            float2 p0, p1, q0, q1;
            p0.x = __uint_as_float(f2tf32(w0 * sigf(acc0[n].x + b0)));
            p0.y = __uint_as_float(f2tf32(w0 * sigf(acc0[n].z + b0)));
            p1.x = __uint_as_float(f2tf32(w1 * sigf(acc0[n].y + b1)));
            p1.y = __uint_as_float(f2tf32(w1 * sigf(acc0[n].w + b1)));
            q0.x = __uint_as_float(f2tf32(w0 * sigf(acc1[n].x + b0)));
            q0.y = __uint_as_float(f2tf32(w0 * sigf(acc1[n].z + b0)));
            q1.x = __uint_as_float(f2tf32(w1 * sigf(acc1[n].y + b1)));
            q1.y = __uint_as_float(f2tf32(w1 * sigf(acc1[n].w + b1)));
            *(float2*)(st0 + n * KST + l0 * 4 + s0b) = p0;
            *(float2*)(st0 + n * KST + l1 * 4 + s1b) = p1;
            *(float2*)(st1 + n * KST + l0 * 4 + s0b) = q0;
            *(float2*)(st1 + n * KST + l1 * 4 + s1b) = q1;
        }
    }
    __syncwarp();

    // ---- GEMM2: OUT = G @ OW + ob ----
    float4 o0[8], o1[8];
#pragma unroll
    for (int n = 0; n < 8; n++) {
        const int c0 = n * 8 + 2 * t;
        o0[n] = make_float4(obs[c0], obs[c0+1], obs[c0], obs[c0+1]);
        o1[n] = o0[n];
    }
#pragma unroll
    for (int k = 0; k < 8; k++) {
        const float4 A0 = *(const float4*)(st0 + k * KST + lane * 4);
        const float4 A1 = *(const float4*)(st1 + k * KST + lane * 4);
#pragma unroll
        for (int n = 0; n < 8; n++) {
            const float2 b = *(const float2*)(owf + ((n * 8 + k) * 32 + lane) * 2);
            mma_tf32(o0[n], __float_as_uint(A0.x), __float_as_uint(A0.y),
                     __float_as_uint(A0.z), __float_as_uint(A0.w),
                     __float_as_uint(b.x), __float_as_uint(b.y));
            mma_tf32(o1[n], __float_as_uint(A1.x), __float_as_uint(A1.y),
                     __float_as_uint(A1.z), __float_as_uint(A1.w),
                     __float_as_uint(b.x), __float_as_uint(b.y));
        }
    }
    __syncwarp();

    // ---- stage outputs row-major into the same strip region ----
#pragma unroll
    for (int n = 0; n < 8; n++) {
        const int c0 = n * 8 + 2 * t;
        *(float2*)(st0 + g * 68 + c0)       = make_float2(o0[n].x, o0[n].y);
        *(float2*)(st0 + (g + 8) * 68 + c0) = make_float2(o0[n].z, o0[n].w);
        *(float2*)(st1 + g * 68 + c0)       = make_float2(o1[n].x, o1[n].y);
        *(float2*)(st1 + (g + 8) * 68 + c0) = make_float2(o1[n].z, o1[n].w);
    }
    __syncwarp();

    // ---- coalesced STG ----
#pragma unroll
    for (int rnd = 0; rnd < 16; rnd++) {
        const int row = w * 32 + rnd * 2 + rsel;
        const int st = row >> 4, rowin = row & 15;
        const float4 v = *(const float4*)(xnf + st * SST + rowin * 68 + c4 * 4);
        *(float4*)(out + ((size_t)(s0 + row) * NRES + r) * CM + c4 * 4) = v;
    }
}

// ---------------------------------------------------------------------------
#define K1_SMEM (27232 * 4)
#define K2_SMEM (25920 * 4)

extern "C" void kernel_launch(void* const* d_in, const int* in_sizes, int n_in,
                              void* d_out, int out_size) {
    (void)in_sizes; (void)n_in; (void)out_size;
    const float* act      = (const float*)d_in[0];
    const float* mask     = (const float*)d_in[1];
    const float* ln_scale = (const float*)d_in[2];
    const float* ln_bias  = (const float*)d_in[3];
    const float* query_w  = (const float*)d_in[4];
    const float* key_w    = (const float*)d_in[5];
    const float* value_w  = (const float*)d_in[6];
    const float* gating_w = (const float*)d_in[7];
    const float* gating_b = (const float*)d_in[8];
    const float* output_w = (const float*)d_in[9];
    const float* output_b = (const float*)d_in[10];
    float* out = (float*)d_out;

    cudaFuncSetAttribute(msa_k1, cudaFuncAttributeMaxDynamicSharedMemorySize, K1_SMEM);
    cudaFuncSetAttribute(msa_k2, cudaFuncAttributeMaxDynamicSharedMemorySize, K2_SMEM);

    msa_k1<<<NRES, 256, K1_SMEM>>>(act, mask, ln_scale, ln_bias, query_w, key_w, value_w);
    msa_k2<<<dim3(NRES, 4), 256, K2_SMEM>>>(act, ln_scale, ln_bias,
                                            gating_w, gating_b, output_w, output_b, out);
}